// round 5
// baseline (speedup 1.0000x reference)
#include <cuda_runtime.h>
#include <cstdint>

// Problem shape (fixed by the reference):
//   graph_lstm_output: [B=4, S=256, C=128] f32   (d_in[0])
//   slic_output:       [B=4, H=512, W=512] i32   (d_in[1])
//   out:               [B, H, W, C] f32
//
// out[b,h,w,:] = graph_lstm_output[b, slic[b,h,w]-1, :]
//
// R3: UNROLL=4 -> 80.4us, DRAM 76.5% (6.06 TB/s), issue 17.7%: residual
// latency exposure. R4 (container died, remeasuring): UNROLL=8, phase-batched
// so 8 independent slic->gather->store chains are in flight per thread.

static constexpr int B = 4;
static constexpr int S = 256;
static constexpr int C = 128;              // 32 float4 per pixel
static constexpr int HW = 512 * 512;       // 2^18 pixels per batch
static constexpr int NPIX = B * HW;        // 2^20
static constexpr int V4_PER_PIX = C / 4;   // 32
static constexpr unsigned TOTAL_V4 = (unsigned)NPIX * V4_PER_PIX;  // 2^25
static constexpr int UNROLL = 8;
static constexpr unsigned CHUNK = TOTAL_V4 / UNROLL;               // 2^22

__global__ __launch_bounds__(256)
void convert2image_gather8(const float4* __restrict__ src,   // [B*S, 32] float4 rows
                           const int*    __restrict__ slic,  // [NPIX]
                           float4*       __restrict__ out)   // [NPIX, 32]
{
    const unsigned t = blockIdx.x * blockDim.x + threadIdx.x;  // [0, CHUNK)
    const unsigned lane = t & 31;  // same for all chunks (CHUNK is 32-aligned)

    // Phase 1: 8 independent slic loads (warp-uniform broadcasts) + addr math.
    // __ldcs: slic is streamed once; keep L1 free for the 512 KB table.
    const float4* rowp[UNROLL];
    #pragma unroll
    for (int i = 0; i < UNROLL; i++) {
        unsigned pix = (t + (unsigned)i * CHUNK) >> 5;  // float4 -> pixel
        int seg = __ldcs(&slic[pix]) - 1;               // 0-based segment
        unsigned b = pix >> 18;                         // pixel / (512*512)
        rowp[i] = src + (((b << 8) + (unsigned)seg) << 5);  // *32 float4
    }

    // Phase 2: 8 independent gather loads (table is L2/L1-hot, 512 KB total).
    float4 v[UNROLL];
    #pragma unroll
    for (int i = 0; i < UNROLL; i++)
        v[i] = __ldg(&rowp[i][lane]);

    // Phase 3: 8 coalesced streaming stores (write-once, evict-first).
    #pragma unroll
    for (int i = 0; i < UNROLL; i++)
        __stcs(&out[t + (unsigned)i * CHUNK], v[i]);
}

extern "C" void kernel_launch(void* const* d_in, const int* in_sizes, int n_in,
                              void* d_out, int out_size)
{
    const float4* src  = (const float4*)d_in[0];
    const int*    slic = (const int*)d_in[1];
    float4*       out  = (float4*)d_out;

    const int threads = 256;
    const int blocks  = CHUNK / threads;   // 2^22 / 256 = 16384, exact
    convert2image_gather8<<<blocks, threads>>>(src, slic, out);
}